// round 9
// baseline (speedup 1.0000x reference)
#include <cuda_runtime.h>
#include <cstdint>

// Problem constants
constexpr int C   = 128;
constexpr int CF  = 16;
constexpr int N   = 256;
constexpr int K   = 15;
constexpr int TPB = 512;   // (pixel, half)

constexpr int XO_PITCH   = 132;  // [N][C] patch tile; 16B-aligned rows, float4 conflict-free
constexpr int XN_PITCH   = 20;   // [N][18] normalized feats, float4-aligned rows
constexpr int AC_PITCH   = 20;   // [N][18] pre-norm feats, float4-aligned rows
constexpr int KPITCH     = 17;   // per-thread top-16 key lists
constexpr int CAND_PITCH = 20;   // merged candidate bytes per row

// shared memory layout (bytes)
constexpr int OFF_INV   = 0;                              // 256 double  = 2048
constexpr int OFF_XO    = 2048;                           // 256*132*4   = 135168
constexpr int OFF_FW    = OFF_XO + N * XO_PITCH * 4;      // 8192
constexpr int OFF_FB    = OFF_FW + CF * C * 4;            // 64
constexpr int OFF_XNF   = OFF_FB + CF * 4;                // 256*20*4    = 20480
constexpr int OFF_ACC   = OFF_XNF + N * XN_PITCH * 4;     // 256*20*4    = 20480
constexpr int OFF_UNION = OFF_ACC + N * AC_PITCH * 4;     // max(keys 34816, simk 36864)
constexpr int OFF_CAND  = OFF_UNION + 36864;              // 256*20 u8   = 5120
constexpr int SMEM_BYTES = OFF_CAND + N * CAND_PITCH;     // 228416 B (< 232448 max)

// monotone float<->u32 (order-preserving)
__device__ __forceinline__ uint32_t fmono(float f) {
    uint32_t b = __float_as_uint(f);
    return (b & 0x80000000u) ? ~b : (b | 0x80000000u);
}
// monotone double<->u64
__device__ __forceinline__ uint64_t dmono(double d) {
    uint64_t b = (uint64_t)__double_as_longlong(d);
    return (b & 0x8000000000000000ull) ? ~b : (b | 0x8000000000000000ull);
}
__device__ __forceinline__ double dunmono(uint64_t u) {
    uint64_t b = (u & 0x8000000000000000ull) ? (u & 0x7FFFFFFFFFFFFFFFull) : ~u;
    return __longlong_as_double((long long)b);
}

__global__ void __launch_bounds__(TPB, 1)
gnn_local_cluster_kernel(const float* __restrict__ x_in,
                         const float* __restrict__ f_w,
                         const float* __restrict__ f_b,
                         const float* __restrict__ edge_alpha,
                         const float* __restrict__ edge_beta,
                         float* __restrict__ out)
{
    extern __shared__ char smraw[];
    double*   invn = reinterpret_cast<double*>(smraw + OFF_INV);    // [N] 1/norm fp64
    float*    xo   = reinterpret_cast<float*>(smraw + OFF_XO);      // [N][132]
    float*    fw   = reinterpret_cast<float*>(smraw + OFF_FW);      // [16][128]
    float*    fb   = reinterpret_cast<float*>(smraw + OFF_FB);      // [16]
    float*    xnf  = reinterpret_cast<float*>(smraw + OFF_XNF);     // [N][20] normalized
    float*    accf = reinterpret_cast<float*>(smraw + OFF_ACC);     // [N][20] pre-norm; later weights
    uint32_t* keys = reinterpret_cast<uint32_t*>(smraw + OFF_UNION);// [512][17] pass-1 keys
    uint64_t* simk = reinterpret_cast<uint64_t*>(smraw + OFF_UNION);// [256][18] rerank keys (after)
    uint8_t*  cand = reinterpret_cast<uint8_t*>(smraw + OFF_CAND);  // [256][20] candidate rows

    const int p   = blockIdx.x;
    const int b   = p / 49;
    const int wg  = (p / 7) % 7;
    const int hg  = p % 7;
    const int tid = threadIdx.x;
    const int n   = tid & 255;     // pixel
    const int h   = tid >> 8;      // half id (0/1)

    const int gbase = ((b * C * 112) + wg * 16) * 112 + hg * 16;

    // ---- load weights + patch tile ----
    for (int idx = tid; idx < CF * C; idx += TPB) fw[idx] = f_w[idx];
    if (tid < CF) fb[tid] = f_b[tid];
    for (int idx = tid; idx < C * N; idx += TPB) {
        int c = idx >> 8;
        int nn = idx & 255;
        int i = nn >> 4, j = nn & 15;
        xo[nn * XO_PITCH + c] = x_in[gbase + c * (112 * 112) + i * 112 + j];
    }
    __syncthreads();

    // ---- conv: thread (n,h) computes channels h*8..h*8+7 of pixel n ----
    // float4 row reads (conflict-free with pitch 132); per-channel order = c
    // ascending FMA from 0, bias after — bitwise-identical to R6/R8.
    {
        float acc[8];
        #pragma unroll
        for (int d = 0; d < 8; ++d) acc[d] = 0.0f;
        const float4* xr4 = reinterpret_cast<const float4*>(xo + n * XO_PITCH);
        const float*  fwh = fw + (h * 8) * C;
        #pragma unroll 4
        for (int c4 = 0; c4 < 32; ++c4) {
            float4 xv = xr4[c4];
            const int c = c4 * 4;
            #pragma unroll
            for (int d = 0; d < 8; ++d) acc[d] = __fmaf_rn(xv.x, fwh[d * C + c],     acc[d]);
            #pragma unroll
            for (int d = 0; d < 8; ++d) acc[d] = __fmaf_rn(xv.y, fwh[d * C + c + 1], acc[d]);
            #pragma unroll
            for (int d = 0; d < 8; ++d) acc[d] = __fmaf_rn(xv.z, fwh[d * C + c + 2], acc[d]);
            #pragma unroll
            for (int d = 0; d < 8; ++d) acc[d] = __fmaf_rn(xv.w, fwh[d * C + c + 3], acc[d]);
        }
        float* aw = accf + n * AC_PITCH + h * 8;
        #pragma unroll
        for (int d = 0; d < 8; ++d) aw[d] = __fadd_rn(acc[d], fb[h * 8 + d]);
    }
    __syncthreads();

    // ---- norm (h==0): fp64-exact inverse norm; fp32 normalized feats ----
    if (h == 0) {
        const int i = n >> 4, j = n & 15;
        const float sd    = __fsqrt_rn(__fdiv_rn(5440.0f, 255.0f));
        const float denom = __fadd_rn(sd, 1e-5f);
        const float g0 = __fdiv_rn((float)i - 7.5f, denom);
        const float g1 = __fdiv_rn((float)j - 7.5f, denom);
        float* ar = accf + n * AC_PITCH;
        ar[16] = g0; ar[17] = g1; ar[18] = 0.0f; ar[19] = 0.0f;

        double ss = 0.0;
        #pragma unroll
        for (int d = 0; d < CF; ++d) ss = fma((double)ar[d], (double)ar[d], ss);
        ss = fma((double)g0, (double)g0, ss);
        ss = fma((double)g1, (double)g1, ss);
        double nd = sqrt(ss);
        if (nd < 1e-8) nd = 1e-8;
        double inv = 1.0 / nd;
        invn[n] = inv;
        const float rinv = (float)inv;

        float* xw = xnf + n * XN_PITCH;
        #pragma unroll
        for (int d = 0; d < CF; ++d) xw[d] = ar[d] * rinv;
        xw[16] = g0 * rinv; xw[17] = g1 * rinv; xw[18] = 0.0f; xw[19] = 0.0f;
    }
    __syncthreads();

    // ---- pass 1: row n vs candidates [h*128, h*128+128), packed top-16 ----
    {
        float rreg[18];
        const float* xr = xnf + n * XN_PITCH;
        #pragma unroll
        for (int d = 0; d < 18; ++d) rreg[d] = xr[d];

        uint32_t kb[16];
        #pragma unroll
        for (int k = 0; k < 16; ++k) kb[k] = 0;

        const int mbase = h * 128;
        for (int mm = 0; mm < 128; ++mm) {
            const int m = mbase + mm;
            const float4* xm4 = reinterpret_cast<const float4*>(xnf + m * XN_PITCH);
            float4 v0 = xm4[0], v1 = xm4[1], v2 = xm4[2], v3 = xm4[3];  // broadcast
            float2 v4 = *reinterpret_cast<const float2*>(xnf + m * XN_PITCH + 16);
            float s0 = 0.f, s1 = 0.f, s2 = 0.f, s3 = 0.f;
            s0 = __fmaf_rn(rreg[0],  v0.x, s0); s1 = __fmaf_rn(rreg[1],  v0.y, s1);
            s2 = __fmaf_rn(rreg[2],  v0.z, s2); s3 = __fmaf_rn(rreg[3],  v0.w, s3);
            s0 = __fmaf_rn(rreg[4],  v1.x, s0); s1 = __fmaf_rn(rreg[5],  v1.y, s1);
            s2 = __fmaf_rn(rreg[6],  v1.z, s2); s3 = __fmaf_rn(rreg[7],  v1.w, s3);
            s0 = __fmaf_rn(rreg[8],  v2.x, s0); s1 = __fmaf_rn(rreg[9],  v2.y, s1);
            s2 = __fmaf_rn(rreg[10], v2.z, s2); s3 = __fmaf_rn(rreg[11], v2.w, s3);
            s0 = __fmaf_rn(rreg[12], v3.x, s0); s1 = __fmaf_rn(rreg[13], v3.y, s1);
            s2 = __fmaf_rn(rreg[14], v3.z, s2); s3 = __fmaf_rn(rreg[15], v3.w, s3);
            s0 = __fmaf_rn(rreg[16], v4.x, s0); s1 = __fmaf_rn(rreg[17], v4.y, s1);
            float s = __fadd_rn(__fadd_rn(s0, s1), __fadd_rn(s2, s3));

            uint32_t key = (fmono(s) & 0xFFFFFF00u) | (uint32_t)(255 - m);
            if (key > kb[15]) {
                uint32_t v = key;
                #pragma unroll
                for (int k = 0; k < 16; ++k) {
                    uint32_t mx = (v > kb[k]) ? v : kb[k];
                    uint32_t mn = (v > kb[k]) ? kb[k] : v;
                    kb[k] = mx; v = mn;
                }
            }
        }
        uint32_t* kr = keys + tid * KPITCH;
        #pragma unroll
        for (int k = 0; k < 16; ++k) kr[k] = kb[k];
    }
    __syncthreads();

    // ---- merge halves -> 18-candidate superset (h==0) ----
    if (h == 0) {
        const uint32_t* la = keys + n * KPITCH;
        const uint32_t* lb = keys + (n + 256) * KPITCH;
        uint8_t* cr = cand + n * CAND_PITCH;
        int ia = 0, ib = 0;
        #pragma unroll
        for (int k = 0; k < 18; ++k) {
            uint32_t va = (ia < 16) ? la[ia] : 0u;
            uint32_t vb = (ib < 16) ? lb[ib] : 0u;
            bool ta = (va >= vb);
            uint32_t v = ta ? va : vb;
            cr[k] = (uint8_t)(255u - (v & 0xFFu));
            ia += ta; ib += !ta;
        }
    }
    __syncthreads();   // keys region dead; simk region live from here

    // ---- df64 rerank: thread (n,h) does candidates h*9..h*9+8 ----
    {
        float ra[20];
        {
            const float4* ar4 = reinterpret_cast<const float4*>(accf + n * AC_PITCH);
            #pragma unroll
            for (int q = 0; q < 5; ++q)
                reinterpret_cast<float4*>(ra)[q] = ar4[q];
        }
        const double inv_n = invn[n];
        const uint8_t* cr = cand + n * CAND_PITCH;
        uint64_t* sk = simk + n * 18 + h * 9;

        #pragma unroll 1
        for (int t = 0; t < 9; ++t) {
            const int m = (int)cr[h * 9 + t];
            float am[20];
            {
                const float4* am4 = reinterpret_cast<const float4*>(accf + m * AC_PITCH);
                #pragma unroll
                for (int q = 0; q < 5; ++q)
                    reinterpret_cast<float4*>(am)[q] = am4[q];
            }
            // Dot2 (compensated fp32 dot): error ~1e-12, all on FMA pipe
            float sh = 0.0f, sl = 0.0f;
            #pragma unroll
            for (int d = 0; d < 18; ++d) {
                float av = ra[d], bv = am[d];
                float ph = __fmul_rn(av, bv);
                float pl = __fmaf_rn(av, bv, -ph);
                float tt = __fadd_rn(sh, ph);
                float zz = __fsub_rn(tt, sh);
                float ee = __fadd_rn(__fsub_rn(sh, __fsub_rn(tt, zz)),
                                     __fsub_rn(ph, zz));
                sh = tt;
                sl = __fadd_rn(sl, __fadd_rn(ee, pl));
            }
            double sim = ((double)sh + (double)sl) * inv_n * invn[m];
            sk[t] = (dmono(sim) & ~0xFFull) | (uint64_t)(255 - m);
        }
    }
    __syncthreads();

    // ---- top-15 select + sigmoid/softmax (h==0); stash weights in accf ----
    if (h == 0) {
        const uint64_t* sr = simk + n * 18;
        uint64_t top[K];
        #pragma unroll
        for (int k = 0; k < K; ++k) top[k] = 0;
        #pragma unroll
        for (int t = 0; t < 18; ++t) {
            uint64_t u = sr[t];
            if (u > top[K - 1]) {
                #pragma unroll
                for (int k = 0; k < K; ++k) {
                    uint64_t mx = (u > top[k]) ? u : top[k];
                    uint64_t mn = (u > top[k]) ? top[k] : u;
                    top[k] = mx; u = mn;
                }
            }
        }
        float sims[K]; int rows[K];
        #pragma unroll
        for (int k = 0; k < K; ++k) {
            rows[k] = 255 - (int)(top[k] & 0xFFull);
            sims[k] = (float)dunmono((top[k] & ~0xFFull) | 0x80ull);
        }

        const float alpha = edge_alpha[0];
        const float beta  = edge_beta[0];
        float wn_[K];
        float wmax = -1e30f;
        #pragma unroll
        for (int k = 0; k < K; ++k) {
            float z  = __fadd_rn(beta, __fmul_rn(alpha, sims[k]));
            float wv = __fdiv_rn(1.0f, __fadd_rn(1.0f, expf(-z)));
            wn_[k] = wv;
            wmax = fmaxf(wmax, wv);
        }
        float wsum = 0.0f;
        #pragma unroll
        for (int k = 0; k < K; ++k) {
            wn_[k] = expf(__fadd_rn(wn_[k], -wmax));
            wsum = __fadd_rn(wsum, wn_[k]);
        }
        float* wrow = accf + n * AC_PITCH;   // accf dead -> reuse for weights
        uint8_t* cr = cand + n * CAND_PITCH; // overwrite with final rows
        #pragma unroll
        for (int k = 0; k < K; ++k) {
            wrow[k] = __fdiv_rn(wn_[k], wsum);
            cr[k]   = (uint8_t)rows[k];
        }
    }
    __syncthreads();

    // ---- cooperative gather: warp handles 16 pixels; per pixel all lanes
    //      read the SAME neighbor row as conflict-free LDS.128 (lane = 4 ch) ----
    {
        const int wid  = tid >> 5;
        const int lane = tid & 31;
        const float4* xo4 = reinterpret_cast<const float4*>(xo);
        #pragma unroll 1
        for (int px = 0; px < 16; ++px) {
            const int n2 = wid * 16 + px;
            const float*   wrow = accf + n2 * AC_PITCH;
            const uint8_t* cr   = cand + n2 * CAND_PITCH;
            float4 o = make_float4(0.f, 0.f, 0.f, 0.f);
            #pragma unroll
            for (int k = 0; k < K; ++k) {
                const float wk  = wrow[k];                      // broadcast
                const int   row = (int)cr[k];                   // broadcast
                float4 v = xo4[row * (XO_PITCH / 4) + lane];    // conflict-free
                o.x = __fmaf_rn(wk, v.x, o.x);
                o.y = __fmaf_rn(wk, v.y, o.y);
                o.z = __fmaf_rn(wk, v.z, o.z);
                o.w = __fmaf_rn(wk, v.w, o.w);
            }
            const int i = n2 >> 4, j = n2 & 15;
            float* outp = out + gbase + i * 112 + j + (lane * 4) * (112 * 112);
            outp[0]              = o.x;
            outp[112 * 112]      = o.y;
            outp[2 * 112 * 112]  = o.z;
            outp[3 * 112 * 112]  = o.w;
        }
    }
}

extern "C" void kernel_launch(void* const* d_in, const int* in_sizes, int n_in,
                              void* d_out, int out_size) {
    const float* x_in = (const float*)d_in[0];
    const float* f_w  = (const float*)d_in[1];
    const float* f_b  = (const float*)d_in[2];
    const float* ea   = (const float*)d_in[3];
    const float* eb   = (const float*)d_in[4];
    float* out = (float*)d_out;

    cudaFuncSetAttribute(gnn_local_cluster_kernel,
                         cudaFuncAttributeMaxDynamicSharedMemorySize, SMEM_BYTES);
    gnn_local_cluster_kernel<<<196, TPB, SMEM_BYTES>>>(x_in, f_w, f_b, ea, eb, out);
}

// round 10
// speedup vs baseline: 1.2906x; 1.2906x over previous
#include <cuda_runtime.h>
#include <cstdint>

// Problem constants
constexpr int C   = 128;
constexpr int CF  = 16;
constexpr int N   = 256;
constexpr int K   = 15;
constexpr int TPB = 512;   // (pixel, half)

constexpr int XO_PITCH   = 132;  // [N][C] patch tile; 16B-aligned rows, float4 conflict-free
constexpr int XN_PITCH   = 20;   // [N][18] normalized feats, float4-aligned rows
constexpr int AC_PITCH   = 20;   // [N][18] pre-norm feats, float4-aligned rows
constexpr int KPITCH     = 17;   // per-thread top-16 key lists
constexpr int CAND_PITCH = 20;   // merged candidate bytes per row

// shared memory layout (bytes)
constexpr int OFF_INV   = 0;                              // 256 double  = 2048
constexpr int OFF_XO    = 2048;                           // 256*132*4   = 135168
constexpr int OFF_FW    = OFF_XO + N * XO_PITCH * 4;      // 8192
constexpr int OFF_FB    = OFF_FW + CF * C * 4;            // 64
constexpr int OFF_XNF   = OFF_FB + CF * 4;                // 256*20*4    = 20480
constexpr int OFF_ACC   = OFF_XNF + N * XN_PITCH * 4;     // 256*20*4    = 20480
constexpr int OFF_UNION = OFF_ACC + N * AC_PITCH * 4;     // keys 34816 | simk 36864 | staging 32768
constexpr int OFF_CAND  = OFF_UNION + 36864;              // 256*20 u8   = 5120
constexpr int SMEM_BYTES = OFF_CAND + N * CAND_PITCH;     // 228416 B (< 232448 max)

// monotone float<->u32 (order-preserving)
__device__ __forceinline__ uint32_t fmono(float f) {
    uint32_t b = __float_as_uint(f);
    return (b & 0x80000000u) ? ~b : (b | 0x80000000u);
}
// monotone double<->u64
__device__ __forceinline__ uint64_t dmono(double d) {
    uint64_t b = (uint64_t)__double_as_longlong(d);
    return (b & 0x8000000000000000ull) ? ~b : (b | 0x8000000000000000ull);
}
__device__ __forceinline__ double dunmono(uint64_t u) {
    uint64_t b = (u & 0x8000000000000000ull) ? (u & 0x7FFFFFFFFFFFFFFFull) : ~u;
    return __longlong_as_double((long long)b);
}

// staging swizzle: conflict-free for channel-lane writes AND pixel-lane reads
__device__ __forceinline__ int stg_off(int c, int px) {
    return c * 64 + ((px + (c >> 2) + 8 * (c & 3)) & 63);
}

__global__ void __launch_bounds__(TPB, 1)
gnn_local_cluster_kernel(const float* __restrict__ x_in,
                         const float* __restrict__ f_w,
                         const float* __restrict__ f_b,
                         const float* __restrict__ edge_alpha,
                         const float* __restrict__ edge_beta,
                         float* __restrict__ out)
{
    extern __shared__ char smraw[];
    double*   invn = reinterpret_cast<double*>(smraw + OFF_INV);    // [N] 1/norm fp64
    float*    xo   = reinterpret_cast<float*>(smraw + OFF_XO);      // [N][132]
    float*    fw   = reinterpret_cast<float*>(smraw + OFF_FW);      // [16][128]
    float*    fb   = reinterpret_cast<float*>(smraw + OFF_FB);      // [16]
    float*    xnf  = reinterpret_cast<float*>(smraw + OFF_XNF);     // [N][20] normalized
    float*    accf = reinterpret_cast<float*>(smraw + OFF_ACC);     // [N][20] pre-norm; later weights
    uint32_t* keys = reinterpret_cast<uint32_t*>(smraw + OFF_UNION);// [512][17] pass-1 keys
    uint64_t* simk = reinterpret_cast<uint64_t*>(smraw + OFF_UNION);// [256][18] rerank keys
    float*    stg  = reinterpret_cast<float*>(smraw + OFF_UNION);   // [128][64] gather staging
    uint8_t*  cand = reinterpret_cast<uint8_t*>(smraw + OFF_CAND);  // [256][20] candidate rows

    const int p   = blockIdx.x;
    const int b   = p / 49;
    const int wg  = (p / 7) % 7;
    const int hg  = p % 7;
    const int tid = threadIdx.x;
    const int n   = tid & 255;     // pixel
    const int h   = tid >> 8;      // half id (0/1)

    const int gbase = ((b * C * 112) + wg * 16) * 112 + hg * 16;

    // ---- load weights + patch tile ----
    for (int idx = tid; idx < CF * C; idx += TPB) fw[idx] = f_w[idx];
    if (tid < CF) fb[tid] = f_b[tid];
    for (int idx = tid; idx < C * N; idx += TPB) {
        int c = idx >> 8;
        int nn = idx & 255;
        int i = nn >> 4, j = nn & 15;
        xo[nn * XO_PITCH + c] = x_in[gbase + c * (112 * 112) + i * 112 + j];
    }
    __syncthreads();

    // ---- conv: thread (n,h) computes channels h*8..h*8+7 of pixel n ----
    // float4 row reads (conflict-free, pitch 132); per-channel order = c ascending
    // FMA from 0, bias after — bitwise-identical to R6/R8.
    {
        float acc[8];
        #pragma unroll
        for (int d = 0; d < 8; ++d) acc[d] = 0.0f;
        const float4* xr4 = reinterpret_cast<const float4*>(xo + n * XO_PITCH);
        const float*  fwh = fw + (h * 8) * C;
        #pragma unroll 4
        for (int c4 = 0; c4 < 32; ++c4) {
            float4 xv = xr4[c4];
            const int c = c4 * 4;
            #pragma unroll
            for (int d = 0; d < 8; ++d) acc[d] = __fmaf_rn(xv.x, fwh[d * C + c],     acc[d]);
            #pragma unroll
            for (int d = 0; d < 8; ++d) acc[d] = __fmaf_rn(xv.y, fwh[d * C + c + 1], acc[d]);
            #pragma unroll
            for (int d = 0; d < 8; ++d) acc[d] = __fmaf_rn(xv.z, fwh[d * C + c + 2], acc[d]);
            #pragma unroll
            for (int d = 0; d < 8; ++d) acc[d] = __fmaf_rn(xv.w, fwh[d * C + c + 3], acc[d]);
        }
        float* aw = accf + n * AC_PITCH + h * 8;
        #pragma unroll
        for (int d = 0; d < 8; ++d) aw[d] = __fadd_rn(acc[d], fb[h * 8 + d]);
    }
    __syncthreads();

    // ---- norm (h==0): fp64-exact inverse norm; fp32 normalized feats ----
    if (h == 0) {
        const int i = n >> 4, j = n & 15;
        const float sd    = __fsqrt_rn(__fdiv_rn(5440.0f, 255.0f));
        const float denom = __fadd_rn(sd, 1e-5f);
        const float g0 = __fdiv_rn((float)i - 7.5f, denom);
        const float g1 = __fdiv_rn((float)j - 7.5f, denom);
        float* ar = accf + n * AC_PITCH;
        ar[16] = g0; ar[17] = g1; ar[18] = 0.0f; ar[19] = 0.0f;

        double ss = 0.0;
        #pragma unroll
        for (int d = 0; d < CF; ++d) ss = fma((double)ar[d], (double)ar[d], ss);
        ss = fma((double)g0, (double)g0, ss);
        ss = fma((double)g1, (double)g1, ss);
        double nd = sqrt(ss);
        if (nd < 1e-8) nd = 1e-8;
        double inv = 1.0 / nd;
        invn[n] = inv;
        const float rinv = (float)inv;

        float* xw = xnf + n * XN_PITCH;
        #pragma unroll
        for (int d = 0; d < CF; ++d) xw[d] = ar[d] * rinv;
        xw[16] = g0 * rinv; xw[17] = g1 * rinv; xw[18] = 0.0f; xw[19] = 0.0f;
    }
    __syncthreads();

    // ---- pass 1: row n vs candidates [h*128, h*128+128), packed top-16 ----
    {
        float rreg[18];
        const float* xr = xnf + n * XN_PITCH;
        #pragma unroll
        for (int d = 0; d < 18; ++d) rreg[d] = xr[d];

        uint32_t kb[16];
        #pragma unroll
        for (int k = 0; k < 16; ++k) kb[k] = 0;

        const int mbase = h * 128;
        for (int mm = 0; mm < 128; ++mm) {
            const int m = mbase + mm;
            const float4* xm4 = reinterpret_cast<const float4*>(xnf + m * XN_PITCH);
            float4 v0 = xm4[0], v1 = xm4[1], v2 = xm4[2], v3 = xm4[3];  // broadcast
            float2 v4 = *reinterpret_cast<const float2*>(xnf + m * XN_PITCH + 16);
            float s0 = 0.f, s1 = 0.f, s2 = 0.f, s3 = 0.f;
            s0 = __fmaf_rn(rreg[0],  v0.x, s0); s1 = __fmaf_rn(rreg[1],  v0.y, s1);
            s2 = __fmaf_rn(rreg[2],  v0.z, s2); s3 = __fmaf_rn(rreg[3],  v0.w, s3);
            s0 = __fmaf_rn(rreg[4],  v1.x, s0); s1 = __fmaf_rn(rreg[5],  v1.y, s1);
            s2 = __fmaf_rn(rreg[6],  v1.z, s2); s3 = __fmaf_rn(rreg[7],  v1.w, s3);
            s0 = __fmaf_rn(rreg[8],  v2.x, s0); s1 = __fmaf_rn(rreg[9],  v2.y, s1);
            s2 = __fmaf_rn(rreg[10], v2.z, s2); s3 = __fmaf_rn(rreg[11], v2.w, s3);
            s0 = __fmaf_rn(rreg[12], v3.x, s0); s1 = __fmaf_rn(rreg[13], v3.y, s1);
            s2 = __fmaf_rn(rreg[14], v3.z, s2); s3 = __fmaf_rn(rreg[15], v3.w, s3);
            s0 = __fmaf_rn(rreg[16], v4.x, s0); s1 = __fmaf_rn(rreg[17], v4.y, s1);
            float s = __fadd_rn(__fadd_rn(s0, s1), __fadd_rn(s2, s3));

            uint32_t key = (fmono(s) & 0xFFFFFF00u) | (uint32_t)(255 - m);
            if (key > kb[15]) {
                uint32_t v = key;
                #pragma unroll
                for (int k = 0; k < 16; ++k) {
                    uint32_t mx = (v > kb[k]) ? v : kb[k];
                    uint32_t mn = (v > kb[k]) ? kb[k] : v;
                    kb[k] = mx; v = mn;
                }
            }
        }
        uint32_t* kr = keys + tid * KPITCH;
        #pragma unroll
        for (int k = 0; k < 16; ++k) kr[k] = kb[k];
    }
    __syncthreads();

    // ---- merge halves -> 18-candidate superset (h==0) ----
    if (h == 0) {
        const uint32_t* la = keys + n * KPITCH;
        const uint32_t* lb = keys + (n + 256) * KPITCH;
        uint8_t* cr = cand + n * CAND_PITCH;
        int ia = 0, ib = 0;
        #pragma unroll
        for (int k = 0; k < 18; ++k) {
            uint32_t va = (ia < 16) ? la[ia] : 0u;
            uint32_t vb = (ib < 16) ? lb[ib] : 0u;
            bool ta = (va >= vb);
            uint32_t v = ta ? va : vb;
            cr[k] = (uint8_t)(255u - (v & 0xFFu));
            ia += ta; ib += !ta;
        }
    }
    __syncthreads();   // keys region dead; simk region live from here

    // ---- df64 rerank: thread (n,h) does candidates h*9..h*9+8 ----
    {
        float ra[20];
        {
            const float4* ar4 = reinterpret_cast<const float4*>(accf + n * AC_PITCH);
            #pragma unroll
            for (int q = 0; q < 5; ++q)
                reinterpret_cast<float4*>(ra)[q] = ar4[q];
        }
        const double inv_n = invn[n];
        const uint8_t* cr = cand + n * CAND_PITCH;
        uint64_t* sk = simk + n * 18 + h * 9;

        #pragma unroll 1
        for (int t = 0; t < 9; ++t) {
            const int m = (int)cr[h * 9 + t];
            float am[20];
            {
                const float4* am4 = reinterpret_cast<const float4*>(accf + m * AC_PITCH);
                #pragma unroll
                for (int q = 0; q < 5; ++q)
                    reinterpret_cast<float4*>(am)[q] = am4[q];
            }
            // Dot2 (compensated fp32 dot): error ~1e-12, all on FMA pipe
            float sh = 0.0f, sl = 0.0f;
            #pragma unroll
            for (int d = 0; d < 18; ++d) {
                float av = ra[d], bv = am[d];
                float ph = __fmul_rn(av, bv);
                float pl = __fmaf_rn(av, bv, -ph);
                float tt = __fadd_rn(sh, ph);
                float zz = __fsub_rn(tt, sh);
                float ee = __fadd_rn(__fsub_rn(sh, __fsub_rn(tt, zz)),
                                     __fsub_rn(ph, zz));
                sh = tt;
                sl = __fadd_rn(sl, __fadd_rn(ee, pl));
            }
            double sim = ((double)sh + (double)sl) * inv_n * invn[m];
            sk[t] = (dmono(sim) & ~0xFFull) | (uint64_t)(255 - m);
        }
    }
    __syncthreads();

    // ---- top-15 select + sigmoid/softmax (h==0); stash weights in accf ----
    if (h == 0) {
        const uint64_t* sr = simk + n * 18;
        uint64_t top[K];
        #pragma unroll
        for (int k = 0; k < K; ++k) top[k] = 0;
        #pragma unroll
        for (int t = 0; t < 18; ++t) {
            uint64_t u = sr[t];
            if (u > top[K - 1]) {
                #pragma unroll
                for (int k = 0; k < K; ++k) {
                    uint64_t mx = (u > top[k]) ? u : top[k];
                    uint64_t mn = (u > top[k]) ? top[k] : u;
                    top[k] = mx; u = mn;
                }
            }
        }
        float sims[K]; int rows[K];
        #pragma unroll
        for (int k = 0; k < K; ++k) {
            rows[k] = 255 - (int)(top[k] & 0xFFull);
            sims[k] = (float)dunmono((top[k] & ~0xFFull) | 0x80ull);
        }

        const float alpha = edge_alpha[0];
        const float beta  = edge_beta[0];
        float wn_[K];
        float wmax = -1e30f;
        #pragma unroll
        for (int k = 0; k < K; ++k) {
            float z  = __fadd_rn(beta, __fmul_rn(alpha, sims[k]));
            float wv = __fdiv_rn(1.0f, __fadd_rn(1.0f, expf(-z)));
            wn_[k] = wv;
            wmax = fmaxf(wmax, wv);
        }
        float wsum = 0.0f;
        #pragma unroll
        for (int k = 0; k < K; ++k) {
            wn_[k] = expf(__fadd_rn(wn_[k], -wmax));
            wsum = __fadd_rn(wsum, wn_[k]);
        }
        float* wrow = accf + n * AC_PITCH;   // accf dead -> reuse for weights
        uint8_t* cr = cand + n * CAND_PITCH; // overwrite with final rows
        #pragma unroll
        for (int k = 0; k < K; ++k) {
            wrow[k] = __fdiv_rn(wn_[k], wsum);
            cr[k]   = (uint8_t)rows[k];
        }
    }
    __syncthreads();   // simk dead; staging live from here

    // ---- gather: cooperative conflict-free loads + staged transpose for
    //      coalesced stores. 4 groups of 64 pixels through the staging buffer.
    {
        const int wid  = tid >> 5;
        const int lane = tid & 31;
        const float4* xo4 = reinterpret_cast<const float4*>(xo);

        #pragma unroll 1
        for (int g = 0; g < 4; ++g) {
            // each warp gathers 4 pixels; all lanes read the SAME neighbor row
            // as one conflict-free LDS.128 (lane = channel quad)
            #pragma unroll
            for (int px = 0; px < 4; ++px) {
                const int pl = wid * 4 + px;      // pixel-local 0..63
                const int n2 = g * 64 + pl;
                const float*   wrow = accf + n2 * AC_PITCH;
                const uint8_t* cr   = cand + n2 * CAND_PITCH;
                float4 o = make_float4(0.f, 0.f, 0.f, 0.f);
                #pragma unroll
                for (int k = 0; k < K; ++k) {
                    const float wk  = wrow[k];                   // broadcast
                    const int   row = (int)cr[k];                // broadcast
                    float4 v = xo4[row * (XO_PITCH / 4) + lane]; // conflict-free
                    o.x = __fmaf_rn(wk, v.x, o.x);
                    o.y = __fmaf_rn(wk, v.y, o.y);
                    o.z = __fmaf_rn(wk, v.z, o.z);
                    o.w = __fmaf_rn(wk, v.w, o.w);
                }
                const int c0 = lane * 4;
                stg[stg_off(c0 + 0, pl)] = o.x;   // conflict-free writes
                stg[stg_off(c0 + 1, pl)] = o.y;
                stg[stg_off(c0 + 2, pl)] = o.z;
                stg[stg_off(c0 + 3, pl)] = o.w;
            }
            __syncthreads();
            // coalesced store: warp = 32 consecutive pixels at fixed channel
            #pragma unroll
            for (int t = 0; t < 16; ++t) {
                const int idx = t * 512 + tid;
                const int c  = idx >> 6;
                const int pl = idx & 63;
                const int n2 = g * 64 + pl;
                const int i = n2 >> 4, j = n2 & 15;
                out[gbase + c * (112 * 112) + i * 112 + j] = stg[stg_off(c, pl)];
            }
            __syncthreads();
        }
    }
}

extern "C" void kernel_launch(void* const* d_in, const int* in_sizes, int n_in,
                              void* d_out, int out_size) {
    const float* x_in = (const float*)d_in[0];
    const float* f_w  = (const float*)d_in[1];
    const float* f_b  = (const float*)d_in[2];
    const float* ea   = (const float*)d_in[3];
    const float* eb   = (const float*)d_in[4];
    float* out = (float*)d_out;

    cudaFuncSetAttribute(gnn_local_cluster_kernel,
                         cudaFuncAttributeMaxDynamicSharedMemorySize, SMEM_BYTES);
    gnn_local_cluster_kernel<<<196, TPB, SMEM_BYTES>>>(x_in, f_w, f_b, ea, eb, out);
}